// round 1
// baseline (speedup 1.0000x reference)
#include <cuda_runtime.h>
#include <math.h>

#define B_   16
#define L_   1024
#define D_   512
#define E_   8
#define DFF_ 2048

// Per-sample selected expert (written by router kernel, read by GEMMs).
__device__ int g_top1[B_];
// Intermediate activations h = relu(x @ W1 + b1): 16*1024*2048 floats = 134 MB.
__device__ float g_h[(size_t)B_ * L_ * DFF_];

// ---------------------------------------------------------------------------
// Router + balance loss. Tiny (B=16, E=8): one thread.
// ---------------------------------------------------------------------------
__global__ void router_kernel(const int* __restrict__ view_ids,
                              const int* __restrict__ visit_ids,
                              const float* __restrict__ router_view,
                              const float* __restrict__ router_visit,
                              float* loss_out) {
    float load[E_];
#pragma unroll
    for (int e = 0; e < E_; e++) load[e] = 0.0f;

    for (int b = 0; b < B_; b++) {
        const int vi = view_ids[b];
        const int vs = visit_ids[b];
        float lg[E_];
        float m = -1e30f;
        int am = 0;
#pragma unroll
        for (int e = 0; e < E_; e++) {
            lg[e] = router_view[vi * E_ + e] + router_visit[vs * E_ + e];
            if (lg[e] > m) { m = lg[e]; am = e; }
        }
        g_top1[b] = am;
        float s = 0.0f;
#pragma unroll
        for (int e = 0; e < E_; e++) { lg[e] = expf(lg[e] - m); s += lg[e]; }
        const float inv = 1.0f / s;
#pragma unroll
        for (int e = 0; e < E_; e++) load[e] += lg[e] * inv;
    }

    float loss = 0.0f;
#pragma unroll
    for (int e = 0; e < E_; e++) {
        const float ld = load[e] * (1.0f / (float)B_);
        loss -= ld * logf(ld);
    }
    if (loss_out) *loss_out = loss;
}

// ---------------------------------------------------------------------------
// Tiled fp32 SGEMM with per-sample expert weight selection.
//   Y[b] = act( X[b] (MxK) @ W[e_b] (KxN) + bias[e_b] )
// BM=BN=128, BK=16, 256 threads, 8x8 per thread.
// ---------------------------------------------------------------------------
template <bool RELU>
__global__ void __launch_bounds__(256)
sgemm_expert(const float* __restrict__ Xall,
             const float* __restrict__ Wall,
             const float* __restrict__ Biasall,
             float* __restrict__ Yall,
             int M, int N, int K) {
    constexpr int BM = 128, BN = 128, BK = 16;

    const int b = blockIdx.z;
    const int e = g_top1[b];
    const float* X    = Xall   + (size_t)b * M * K;
    const float* W    = Wall   + (size_t)e * K * N;
    const float* bias = Biasall + (size_t)e * N;
    float* Y          = Yall   + (size_t)b * M * N;

    __shared__ float As[BK][BM];
    __shared__ float Bs[BK][BN];

    const int tid = threadIdx.x;
    const int tx = tid & 15;   // 0..15  -> 8 cols each
    const int ty = tid >> 4;   // 0..15  -> 8 rows each

    const int block_row = blockIdx.y * BM;
    const int block_col = blockIdx.x * BN;

    float acc[8][8];
#pragma unroll
    for (int i = 0; i < 8; i++)
#pragma unroll
        for (int j = 0; j < 8; j++) acc[i][j] = 0.0f;

    for (int k0 = 0; k0 < K; k0 += BK) {
        // Load A tile (BM x BK) transposed into As[BK][BM].
        // BM*BK/4 = 512 float4 loads; 256 threads -> 2 each.
#pragma unroll
        for (int i = 0; i < 2; i++) {
            const int idx = tid + i * 256;
            const int row = idx >> 2;        // / (BK/4)
            const int kq  = idx & 3;         // % (BK/4)
            const float4 v = *(const float4*)&X[(size_t)(block_row + row) * K + k0 + kq * 4];
            As[kq * 4 + 0][row] = v.x;
            As[kq * 4 + 1][row] = v.y;
            As[kq * 4 + 2][row] = v.z;
            As[kq * 4 + 3][row] = v.w;
        }
        // Load B tile (BK x BN): 512 float4, 2 each.
#pragma unroll
        for (int i = 0; i < 2; i++) {
            const int idx  = tid + i * 256;
            const int krow = idx >> 5;       // / (BN/4)
            const int cq   = idx & 31;       // % (BN/4)
            *(float4*)&Bs[krow][cq * 4] =
                *(const float4*)&W[(size_t)(k0 + krow) * N + block_col + cq * 4];
        }
        __syncthreads();

#pragma unroll
        for (int k = 0; k < BK; k++) {
            float a[8], bb[8];
#pragma unroll
            for (int i = 0; i < 8; i++) a[i] = As[k][ty * 8 + i];
#pragma unroll
            for (int j = 0; j < 8; j++) bb[j] = Bs[k][tx * 8 + j];
#pragma unroll
            for (int i = 0; i < 8; i++)
#pragma unroll
                for (int j = 0; j < 8; j++) acc[i][j] = fmaf(a[i], bb[j], acc[i][j]);
        }
        __syncthreads();
    }

    // Epilogue: bias (+ relu), vectorized stores.
#pragma unroll
    for (int i = 0; i < 8; i++) {
        const int row = block_row + ty * 8 + i;
#pragma unroll
        for (int j = 0; j < 8; j += 4) {
            const int col = block_col + tx * 8 + j;
            float4 v;
            v.x = acc[i][j + 0] + bias[col + 0];
            v.y = acc[i][j + 1] + bias[col + 1];
            v.z = acc[i][j + 2] + bias[col + 2];
            v.w = acc[i][j + 3] + bias[col + 3];
            if (RELU) {
                v.x = fmaxf(v.x, 0.0f);
                v.y = fmaxf(v.y, 0.0f);
                v.z = fmaxf(v.z, 0.0f);
                v.w = fmaxf(v.w, 0.0f);
            }
            *(float4*)&Y[(size_t)row * N + col] = v;
        }
    }
}

// ---------------------------------------------------------------------------
// Launch
// ---------------------------------------------------------------------------
extern "C" void kernel_launch(void* const* d_in, const int* in_sizes, int n_in,
                              void* d_out, int out_size) {
    const float* x            = (const float*)d_in[0];
    const int*   view_ids     = (const int*)d_in[1];
    const int*   visit_ids    = (const int*)d_in[2];
    const float* router_view  = (const float*)d_in[3];
    const float* router_visit = (const float*)d_in[4];
    const float* W1           = (const float*)d_in[5];
    const float* b1           = (const float*)d_in[6];
    const float* W2           = (const float*)d_in[7];
    const float* b2           = (const float*)d_in[8];
    float* out = (float*)d_out;

    const size_t out_elems = (size_t)B_ * L_ * D_;
    float* loss_ptr = ((size_t)out_size > out_elems) ? (out + out_elems) : nullptr;

    // Router + loss (also fills g_top1).
    router_kernel<<<1, 1>>>(view_ids, visit_ids, router_view, router_visit, loss_ptr);

    float* h_ptr = nullptr;
    cudaGetSymbolAddress((void**)&h_ptr, g_h);

    // GEMM1: h = relu(x @ W1 + b1)   [per sample: 1024x512 @ 512x2048]
    dim3 g1(DFF_ / 128, L_ / 128, B_);
    sgemm_expert<true><<<g1, 256>>>(x, W1, b1, h_ptr, L_, DFF_, D_);

    // GEMM2: out = h @ W2 + b2       [per sample: 1024x2048 @ 2048x512]
    dim3 g2(D_ / 128, L_ / 128, B_);
    sgemm_expert<false><<<g2, 256>>>(h_ptr, W2, b2, out, L_, D_, DFF_);
}

// round 3
// speedup vs baseline: 3.1478x; 3.1478x over previous
#include <cuda_runtime.h>
#include <math.h>
#include <stdint.h>

#define B_   16
#define L_   1024
#define D_   512
#define E_   8
#define DFF_ 2048

// ---------------------------------------------------------------------------
// Scratch (static __device__ — no allocations allowed)
// ---------------------------------------------------------------------------
__device__ int   g_top1[B_];
__device__ float g_h  [(size_t)B_ * L_ * DFF_];   // relu(x@W1+b1), tf32-rounded
__device__ float g_xr [(size_t)B_ * L_ * D_];     // x rounded to tf32
__device__ float g_w1t[(size_t)E_ * DFF_ * D_];   // W1^T per expert (N x K), tf32
__device__ float g_w2t[(size_t)E_ * D_ * DFF_];   // W2^T per expert (N x K), tf32

__device__ __forceinline__ uint32_t smem_to_u32(const void* p) {
    uint32_t a;
    asm("{ .reg .u64 t; cvta.to.shared.u64 t, %1; cvt.u32.u64 %0, t; }" : "=r"(a) : "l"(p));
    return a;
}
__device__ __forceinline__ float to_tf32(float x) {
    uint32_t u;
    asm("cvt.rna.tf32.f32 %0, %1;" : "=r"(u) : "f"(x));
    return __uint_as_float(u);
}
__device__ __forceinline__ void cp_async16(uint32_t dst, const void* src) {
    asm volatile("cp.async.cg.shared.global [%0], [%1], 16;" :: "r"(dst), "l"(src) : "memory");
}
__device__ __forceinline__ void ldmatrix_x4(uint32_t& r0, uint32_t& r1, uint32_t& r2,
                                            uint32_t& r3, uint32_t addr) {
    asm volatile("ldmatrix.sync.aligned.m8n8.x4.shared.b16 {%0,%1,%2,%3}, [%4];"
                 : "=r"(r0), "=r"(r1), "=r"(r2), "=r"(r3) : "r"(addr));
}
__device__ __forceinline__ void mma_tf32(float& c0, float& c1, float& c2, float& c3,
                                         uint32_t a0, uint32_t a1, uint32_t a2, uint32_t a3,
                                         uint32_t b0, uint32_t b1) {
    asm volatile("mma.sync.aligned.m16n8k8.row.col.f32.tf32.tf32.f32 "
                 "{%0,%1,%2,%3}, {%4,%5,%6,%7}, {%8,%9}, {%0,%1,%2,%3};"
                 : "+f"(c0), "+f"(c1), "+f"(c2), "+f"(c3)
                 : "r"(a0), "r"(a1), "r"(a2), "r"(a3), "r"(b0), "r"(b1));
}

// ---------------------------------------------------------------------------
// Router + balance loss (tiny)
// ---------------------------------------------------------------------------
__global__ void router_kernel(const int* __restrict__ view_ids,
                              const int* __restrict__ visit_ids,
                              const float* __restrict__ router_view,
                              const float* __restrict__ router_visit,
                              float* loss_out) {
    float load[E_];
#pragma unroll
    for (int e = 0; e < E_; e++) load[e] = 0.0f;
    for (int b = 0; b < B_; b++) {
        const int vi = view_ids[b];
        const int vs = visit_ids[b];
        float lg[E_];
        float m = -1e30f; int am = 0;
#pragma unroll
        for (int e = 0; e < E_; e++) {
            lg[e] = router_view[vi * E_ + e] + router_visit[vs * E_ + e];
            if (lg[e] > m) { m = lg[e]; am = e; }
        }
        g_top1[b] = am;
        float s = 0.0f;
#pragma unroll
        for (int e = 0; e < E_; e++) { lg[e] = expf(lg[e] - m); s += lg[e]; }
        const float inv = 1.0f / s;
#pragma unroll
        for (int e = 0; e < E_; e++) load[e] += lg[e] * inv;
    }
    float loss = 0.0f;
#pragma unroll
    for (int e = 0; e < E_; e++) {
        const float ld = load[e] * (1.0f / (float)B_);
        loss -= ld * logf(ld);
    }
    if (loss_out) *loss_out = loss;
}

// ---------------------------------------------------------------------------
// Prep: round x to tf32 (rna)
// ---------------------------------------------------------------------------
__global__ void round_x_kernel(const float4* __restrict__ in, float4* __restrict__ out, int n4) {
    for (int i = blockIdx.x * blockDim.x + threadIdx.x; i < n4; i += gridDim.x * blockDim.x) {
        float4 v = in[i];
        v.x = to_tf32(v.x); v.y = to_tf32(v.y); v.z = to_tf32(v.z); v.w = to_tf32(v.w);
        out[i] = v;
    }
}

// ---------------------------------------------------------------------------
// Prep: per-expert transpose (R x C -> C x R) + tf32 round
// ---------------------------------------------------------------------------
__global__ void transpose_round(const float* __restrict__ in, float* __restrict__ out,
                                int R, int C) {
    __shared__ float t[32][33];
    const int e = blockIdx.z;
    in  += (size_t)e * R * C;
    out += (size_t)e * C * R;
    const int r0 = blockIdx.y * 32, c0 = blockIdx.x * 32;
    const int tx = threadIdx.x;
#pragma unroll
    for (int i = threadIdx.y; i < 32; i += 8)
        t[i][tx] = in[(size_t)(r0 + i) * C + c0 + tx];
    __syncthreads();
#pragma unroll
    for (int i = threadIdx.y; i < 32; i += 8)
        out[(size_t)(c0 + i) * R + r0 + tx] = to_tf32(t[tx][i]);
}

// ---------------------------------------------------------------------------
// TF32 tensor-core GEMM via mma.sync (sm_80+ path, works at compute_103):
//   Y[b] = act( A[b] (MxK row-major) @ B[e_b]^T (NxK K-major) + bias[e_b] )
// CTA tile 128x128x32, 8 warps (warp tile 64x32), 3-stage cp.async pipeline.
// Smem rows padded to 36 floats (144B) -> conflict-free ldmatrix & STS.128.
// ---------------------------------------------------------------------------
#define STAGES 3
#define TILE_BYTES_HALF 18432            // 128 rows * 144B
#define STAGE_BYTES     36864            // A + B

template <bool RELU_ROUND>
__global__ void __launch_bounds__(256)
gemm_tf32_mma(const float* __restrict__ Aall, const float* __restrict__ Ball,
              const float* __restrict__ biasAll, float* __restrict__ Yall,
              int M, int N, int K) {
    extern __shared__ __align__(128) char smem[];
    const uint32_t smem_base = smem_to_u32(smem);

    const int tid  = threadIdx.x;
    const int wid  = tid >> 5;
    const int lane = tid & 31;
    const int warp_m = wid & 1;          // 2 warp rows
    const int warp_n = wid >> 1;         // 4 warp cols
    const int mbase = warp_m * 64;
    const int nbase = warp_n * 32;

    const int b = blockIdx.z;
    const int e = g_top1[b];
    const int block_row = blockIdx.y * 128;
    const int block_col = blockIdx.x * 128;

    const float* Aptr = Aall + (size_t)b * M * K + (size_t)block_row * K;
    const float* Bptr = Ball + (size_t)e * N * K + (size_t)block_col * K;
    const float* bias = biasAll + (size_t)e * N + block_col;
    float* Y = Yall + (size_t)b * M * N;

    const int T = K >> 5;                // BK = 32

    // -------- cp.async tile loader (A and B tiles, 128x32 each) --------
    auto load_tile = [&](int t, int stage) {
        const float* Ag = Aptr + t * 32;
        const float* Bg = Bptr + t * 32;
        const uint32_t sa = smem_base + stage * STAGE_BYTES;
        const uint32_t sb = sa + TILE_BYTES_HALF;
#pragma unroll
        for (int i = 0; i < 4; i++) {
            const int idx = tid + i * 256;      // 0..1023
            const int r = idx >> 3;
            const int q = idx & 7;
            cp_async16(sa + r * 144 + q * 16, Ag + (size_t)r * K + q * 4);
            cp_async16(sb + r * 144 + q * 16, Bg + (size_t)r * K + q * 4);
        }
        asm volatile("cp.async.commit_group;" ::: "memory");
    };

    float acc[4][4][4];
#pragma unroll
    for (int i = 0; i < 4; i++)
#pragma unroll
        for (int j = 0; j < 4; j++)
#pragma unroll
            for (int r = 0; r < 4; r++) acc[i][j][r] = 0.0f;

    // Prefetch
#pragma unroll
    for (int s = 0; s < STAGES - 1; s++)
        if (s < T) load_tile(s, s);

    // Precomputed ldmatrix lane addressing
    const int a_row = mbase + (lane & 15);
    const int a_coff = ((lane >> 4) & 1) * 16;           // +4 floats for a2/a3
    const int b_row_off = (lane & 7) + ((lane >> 4) & 1) * 8;
    const int b_coff = ((lane >> 3) & 1) * 16;           // +4 floats for b1

    for (int t = 0; t < T; t++) {
        if (t + STAGES - 1 < T) load_tile(t + STAGES - 1, (t + STAGES - 1) % STAGES);

        const int remaining = T - 1 - t;
        if (remaining >= 2)      asm volatile("cp.async.wait_group 2;" ::: "memory");
        else if (remaining == 1) asm volatile("cp.async.wait_group 1;" ::: "memory");
        else                     asm volatile("cp.async.wait_group 0;" ::: "memory");
        __syncthreads();

        const uint32_t sa = smem_base + (t % STAGES) * STAGE_BYTES;
        const uint32_t sb = sa + TILE_BYTES_HALF;

#pragma unroll
        for (int ks = 0; ks < 4; ks++) {
            const int kc = ks * 32;                      // byte offset of kstep (8 floats)
            uint32_t af[4][4];
#pragma unroll
            for (int mt = 0; mt < 4; mt++) {
                const uint32_t addr = sa + (a_row + mt * 16) * 144 + kc + a_coff;
                ldmatrix_x4(af[mt][0], af[mt][1], af[mt][2], af[mt][3], addr);
            }
            uint32_t bf[4][2];
#pragma unroll
            for (int p = 0; p < 2; p++) {
                const uint32_t addr = sb + (nbase + p * 16 + b_row_off) * 144 + kc + b_coff;
                ldmatrix_x4(bf[2 * p][0], bf[2 * p][1], bf[2 * p + 1][0], bf[2 * p + 1][1], addr);
            }
#pragma unroll
            for (int mt = 0; mt < 4; mt++)
#pragma unroll
                for (int nt = 0; nt < 4; nt++)
                    mma_tf32(acc[mt][nt][0], acc[mt][nt][1], acc[mt][nt][2], acc[mt][nt][3],
                             af[mt][0], af[mt][1], af[mt][2], af[mt][3],
                             bf[nt][0], bf[nt][1]);
        }
        __syncthreads();
    }

    // -------- Epilogue: bias (+relu+tf32 round), direct float2 stores --------
    const int gid = lane >> 2;          // 0..7
    const int tig = lane & 3;           // 0..3
#pragma unroll
    for (int nt = 0; nt < 4; nt++) {
        const int coll = nbase + nt * 8 + 2 * tig;
        const float2 bv = *(const float2*)&bias[coll];
        const int col = block_col + coll;
#pragma unroll
        for (int mt = 0; mt < 4; mt++) {
            const int row0 = block_row + mbase + mt * 16 + gid;
            float2 v0, v1;
            v0.x = acc[mt][nt][0] + bv.x;
            v0.y = acc[mt][nt][1] + bv.y;
            v1.x = acc[mt][nt][2] + bv.x;
            v1.y = acc[mt][nt][3] + bv.y;
            if (RELU_ROUND) {
                v0.x = to_tf32(fmaxf(v0.x, 0.0f));
                v0.y = to_tf32(fmaxf(v0.y, 0.0f));
                v1.x = to_tf32(fmaxf(v1.x, 0.0f));
                v1.y = to_tf32(fmaxf(v1.y, 0.0f));
            }
            *(float2*)&Y[(size_t)row0 * N + col] = v0;
            *(float2*)&Y[(size_t)(row0 + 8) * N + col] = v1;
        }
    }
}

// ---------------------------------------------------------------------------
// Launch
// ---------------------------------------------------------------------------
extern "C" void kernel_launch(void* const* d_in, const int* in_sizes, int n_in,
                              void* d_out, int out_size) {
    const float* x            = (const float*)d_in[0];
    const int*   view_ids     = (const int*)d_in[1];
    const int*   visit_ids    = (const int*)d_in[2];
    const float* router_view  = (const float*)d_in[3];
    const float* router_visit = (const float*)d_in[4];
    const float* W1           = (const float*)d_in[5];
    const float* b1           = (const float*)d_in[6];
    const float* W2           = (const float*)d_in[7];
    const float* b2           = (const float*)d_in[8];
    float* out = (float*)d_out;

    const size_t out_elems = (size_t)B_ * L_ * D_;
    float* loss_ptr = ((size_t)out_size > out_elems) ? (out + out_elems) : nullptr;

    float *h_ptr, *xr_ptr, *w1t_ptr, *w2t_ptr;
    cudaGetSymbolAddress((void**)&h_ptr,   g_h);
    cudaGetSymbolAddress((void**)&xr_ptr,  g_xr);
    cudaGetSymbolAddress((void**)&w1t_ptr, g_w1t);
    cudaGetSymbolAddress((void**)&w2t_ptr, g_w2t);

    const int SMEM_BYTES = STAGES * STAGE_BYTES;   // 110592
    cudaFuncSetAttribute((const void*)gemm_tf32_mma<true>,
                         cudaFuncAttributeMaxDynamicSharedMemorySize, SMEM_BYTES);
    cudaFuncSetAttribute((const void*)gemm_tf32_mma<false>,
                         cudaFuncAttributeMaxDynamicSharedMemorySize, SMEM_BYTES);

    // Router + loss (fills g_top1)
    router_kernel<<<1, 1>>>(view_ids, visit_ids, router_view, router_visit, loss_ptr);

    // Prep: round x; transpose + round W1, W2 (to N x K, K-major)
    round_x_kernel<<<1024, 256>>>((const float4*)x, (float4*)xr_ptr,
                                  (int)(out_elems / 4));
    transpose_round<<<dim3(DFF_ / 32, D_ / 32, E_), dim3(32, 8)>>>(W1, w1t_ptr, D_, DFF_);
    transpose_round<<<dim3(D_ / 32, DFF_ / 32, E_), dim3(32, 8)>>>(W2, w2t_ptr, DFF_, D_);

    // GEMM1: h = round(relu(x @ W1 + b1))   M=1024, N=2048, K=512
    gemm_tf32_mma<true><<<dim3(DFF_ / 128, L_ / 128, B_), 256, SMEM_BYTES>>>(
        xr_ptr, w1t_ptr, b1, h_ptr, L_, DFF_, D_);

    // GEMM2: out = h @ W2 + b2              M=1024, N=512, K=2048
    gemm_tf32_mma<false><<<dim3(D_ / 128, L_ / 128, B_), 256, SMEM_BYTES>>>(
        h_ptr, w2t_ptr, b2, out, L_, D_, DFF_);
}

// round 4
// speedup vs baseline: 4.9218x; 1.5636x over previous
#include <cuda_runtime.h>
#include <cuda_fp16.h>
#include <math.h>
#include <stdint.h>

#define B_   16
#define L_   1024
#define D_   512
#define E_   8
#define DFF_ 2048

// ---------------------------------------------------------------------------
// Scratch (static __device__ — no allocations allowed)
// ---------------------------------------------------------------------------
__device__ int    g_top1[B_];
__device__ __half g_h  [(size_t)B_ * L_ * DFF_];   // relu(x@W1+b1), fp16
__device__ __half g_xh [(size_t)B_ * L_ * D_];     // x rounded to fp16
__device__ __half g_w1t[(size_t)E_ * DFF_ * D_];   // W1^T per expert (N x K), fp16
__device__ __half g_w2t[(size_t)E_ * D_ * DFF_];   // W2^T per expert (N x K), fp16

__device__ __forceinline__ uint32_t smem_to_u32(const void* p) {
    uint32_t a;
    asm("{ .reg .u64 t; cvta.to.shared.u64 t, %1; cvt.u32.u64 %0, t; }" : "=r"(a) : "l"(p));
    return a;
}
__device__ __forceinline__ void cp_async16(uint32_t dst, const void* src) {
    asm volatile("cp.async.cg.shared.global [%0], [%1], 16;" :: "r"(dst), "l"(src) : "memory");
}
__device__ __forceinline__ void ldmatrix_x4(uint32_t& r0, uint32_t& r1, uint32_t& r2,
                                            uint32_t& r3, uint32_t addr) {
    asm volatile("ldmatrix.sync.aligned.m8n8.x4.shared.b16 {%0,%1,%2,%3}, [%4];"
                 : "=r"(r0), "=r"(r1), "=r"(r2), "=r"(r3) : "r"(addr));
}
__device__ __forceinline__ void mma_f16(float& c0, float& c1, float& c2, float& c3,
                                        uint32_t a0, uint32_t a1, uint32_t a2, uint32_t a3,
                                        uint32_t b0, uint32_t b1) {
    asm volatile("mma.sync.aligned.m16n8k16.row.col.f32.f16.f16.f32 "
                 "{%0,%1,%2,%3}, {%4,%5,%6,%7}, {%8,%9}, {%0,%1,%2,%3};"
                 : "+f"(c0), "+f"(c1), "+f"(c2), "+f"(c3)
                 : "r"(a0), "r"(a1), "r"(a2), "r"(a3), "r"(b0), "r"(b1));
}

// ---------------------------------------------------------------------------
// Router + balance loss (tiny)
// ---------------------------------------------------------------------------
__global__ void router_kernel(const int* __restrict__ view_ids,
                              const int* __restrict__ visit_ids,
                              const float* __restrict__ router_view,
                              const float* __restrict__ router_visit,
                              float* loss_out) {
    float load[E_];
#pragma unroll
    for (int e = 0; e < E_; e++) load[e] = 0.0f;
    for (int b = 0; b < B_; b++) {
        const int vi = view_ids[b];
        const int vs = visit_ids[b];
        float lg[E_];
        float m = -1e30f; int am = 0;
#pragma unroll
        for (int e = 0; e < E_; e++) {
            lg[e] = router_view[vi * E_ + e] + router_visit[vs * E_ + e];
            if (lg[e] > m) { m = lg[e]; am = e; }
        }
        g_top1[b] = am;
        float s = 0.0f;
#pragma unroll
        for (int e = 0; e < E_; e++) { lg[e] = expf(lg[e] - m); s += lg[e]; }
        const float inv = 1.0f / s;
#pragma unroll
        for (int e = 0; e < E_; e++) load[e] += lg[e] * inv;
    }
    float loss = 0.0f;
#pragma unroll
    for (int e = 0; e < E_; e++) {
        const float ld = load[e] * (1.0f / (float)B_);
        loss -= ld * logf(ld);
    }
    if (loss_out) *loss_out = loss;
}

// ---------------------------------------------------------------------------
// Prep: round x to fp16 (rn)
// ---------------------------------------------------------------------------
__global__ void round_x_half(const float4* __restrict__ in, uint2* __restrict__ out, int n4) {
    for (int i = blockIdx.x * blockDim.x + threadIdx.x; i < n4; i += gridDim.x * blockDim.x) {
        const float4 v = in[i];
        const __half2 h01 = __floats2half2_rn(v.x, v.y);
        const __half2 h23 = __floats2half2_rn(v.z, v.w);
        uint2 o;
        o.x = *(const uint32_t*)&h01;
        o.y = *(const uint32_t*)&h23;
        out[i] = o;
    }
}

// ---------------------------------------------------------------------------
// Prep: per-expert transpose (R x C f32 -> C x R fp16)
// ---------------------------------------------------------------------------
__global__ void transpose_half(const float* __restrict__ in, __half* __restrict__ out,
                               int R, int C) {
    __shared__ float t[32][33];
    const int e = blockIdx.z;
    in  += (size_t)e * R * C;
    out += (size_t)e * C * R;
    const int r0 = blockIdx.y * 32, c0 = blockIdx.x * 32;
    const int tx = threadIdx.x;
#pragma unroll
    for (int i = threadIdx.y; i < 32; i += 8)
        t[i][tx] = in[(size_t)(r0 + i) * C + c0 + tx];
    __syncthreads();
#pragma unroll
    for (int i = threadIdx.y; i < 32; i += 8)
        out[(size_t)(c0 + i) * R + r0 + tx] = __float2half_rn(t[tx][i]);
}

// ---------------------------------------------------------------------------
// FP16 tensor-core GEMM via mma.sync m16n8k16 (fp32 accumulate):
//   Y[b] = act( A[b] (MxK row-major fp16) @ B[e_b]^T (NxK K-major fp16) + bias[e_b] )
// CTA tile 128x128x64, 8 warps (warp tile 64x32), 3-stage cp.async pipeline.
// Smem rows padded to 144B -> conflict-free ldmatrix & async stores.
// ---------------------------------------------------------------------------
#define STAGES 3
#define TILE_BYTES_HALF 18432            // 128 rows * 144B
#define STAGE_BYTES     36864            // A + B

// OUT_HALF=true: h output (fp16, relu). false: float output, no relu.
template <bool OUT_HALF>
__global__ void __launch_bounds__(256)
gemm_f16_mma(const __half* __restrict__ Aall, const __half* __restrict__ Ball,
             const float* __restrict__ biasAll, void* __restrict__ Yall,
             int M, int N, int K) {
    extern __shared__ __align__(128) char smem[];
    const uint32_t smem_base = smem_to_u32(smem);

    const int tid  = threadIdx.x;
    const int wid  = tid >> 5;
    const int lane = tid & 31;
    const int warp_m = wid & 1;          // 2 warp rows
    const int warp_n = wid >> 1;         // 4 warp cols
    const int mbase = warp_m * 64;
    const int nbase = warp_n * 32;

    const int b = blockIdx.z;
    const int e = g_top1[b];
    const int block_row = blockIdx.y * 128;
    const int block_col = blockIdx.x * 128;

    const __half* Aptr = Aall + (size_t)b * M * K + (size_t)block_row * K;
    const __half* Bptr = Ball + (size_t)e * N * K + (size_t)block_col * K;
    const float* bias = biasAll + (size_t)e * N + block_col;

    const int T = K >> 6;                // BK = 64

    // -------- cp.async tile loader (A and B tiles, 128 x 64 halves each) ----
    auto load_tile = [&](int t, int stage) {
        const __half* Ag = Aptr + t * 64;
        const __half* Bg = Bptr + t * 64;
        const uint32_t sa = smem_base + stage * STAGE_BYTES;
        const uint32_t sb = sa + TILE_BYTES_HALF;
#pragma unroll
        for (int i = 0; i < 4; i++) {
            const int idx = tid + i * 256;      // 0..1023
            const int r = idx >> 3;
            const int q = idx & 7;              // 16B chunk (8 halves)
            cp_async16(sa + r * 144 + q * 16, Ag + (size_t)r * K + q * 8);
            cp_async16(sb + r * 144 + q * 16, Bg + (size_t)r * K + q * 8);
        }
        asm volatile("cp.async.commit_group;" ::: "memory");
    };

    float acc[4][4][4];
#pragma unroll
    for (int i = 0; i < 4; i++)
#pragma unroll
        for (int j = 0; j < 4; j++)
#pragma unroll
            for (int r = 0; r < 4; r++) acc[i][j][r] = 0.0f;

    // Prefetch
#pragma unroll
    for (int s = 0; s < STAGES - 1; s++)
        if (s < T) load_tile(s, s);

    // ldmatrix lane addressing (byte offsets; k+8 halves = +16B)
    const int a_row = mbase + (lane & 15);
    const int a_coff = ((lane >> 4) & 1) * 16;
    const int b_row_off = (lane & 7) + ((lane >> 4) & 1) * 8;
    const int b_coff = ((lane >> 3) & 1) * 16;

    for (int t = 0; t < T; t++) {
        if (t + STAGES - 1 < T) load_tile(t + STAGES - 1, (t + STAGES - 1) % STAGES);

        const int remaining = T - 1 - t;
        if (remaining >= 2)      asm volatile("cp.async.wait_group 2;" ::: "memory");
        else if (remaining == 1) asm volatile("cp.async.wait_group 1;" ::: "memory");
        else                     asm volatile("cp.async.wait_group 0;" ::: "memory");
        __syncthreads();

        const uint32_t sa = smem_base + (t % STAGES) * STAGE_BYTES;
        const uint32_t sb = sa + TILE_BYTES_HALF;

#pragma unroll
        for (int ks = 0; ks < 4; ks++) {
            const int kc = ks * 32;                      // 16 halves per kstep
            uint32_t af[4][4];
#pragma unroll
            for (int mt = 0; mt < 4; mt++) {
                const uint32_t addr = sa + (a_row + mt * 16) * 144 + kc + a_coff;
                ldmatrix_x4(af[mt][0], af[mt][1], af[mt][2], af[mt][3], addr);
            }
            uint32_t bf[4][2];
#pragma unroll
            for (int p = 0; p < 2; p++) {
                const uint32_t addr = sb + (nbase + p * 16 + b_row_off) * 144 + kc + b_coff;
                ldmatrix_x4(bf[2 * p][0], bf[2 * p][1], bf[2 * p + 1][0], bf[2 * p + 1][1], addr);
            }
#pragma unroll
            for (int mt = 0; mt < 4; mt++)
#pragma unroll
                for (int nt = 0; nt < 4; nt++)
                    mma_f16(acc[mt][nt][0], acc[mt][nt][1], acc[mt][nt][2], acc[mt][nt][3],
                            af[mt][0], af[mt][1], af[mt][2], af[mt][3],
                            bf[nt][0], bf[nt][1]);
        }
        __syncthreads();
    }

    // -------- Epilogue --------
    const int gid = lane >> 2;          // 0..7
    const int tig = lane & 3;           // 0..3
#pragma unroll
    for (int nt = 0; nt < 4; nt++) {
        const int coll = nbase + nt * 8 + 2 * tig;
        const float2 bv = *(const float2*)&bias[coll];
        const int col = block_col + coll;
#pragma unroll
        for (int mt = 0; mt < 4; mt++) {
            const int row0 = block_row + mbase + mt * 16 + gid;
            float2 v0, v1;
            v0.x = acc[mt][nt][0] + bv.x;
            v0.y = acc[mt][nt][1] + bv.y;
            v1.x = acc[mt][nt][2] + bv.x;
            v1.y = acc[mt][nt][3] + bv.y;
            if (OUT_HALF) {
                __half* Y = (__half*)Yall + (size_t)b * M * N;
                const __half2 h0 = __floats2half2_rn(fmaxf(v0.x, 0.0f), fmaxf(v0.y, 0.0f));
                const __half2 h1 = __floats2half2_rn(fmaxf(v1.x, 0.0f), fmaxf(v1.y, 0.0f));
                *(__half2*)&Y[(size_t)row0 * N + col] = h0;
                *(__half2*)&Y[(size_t)(row0 + 8) * N + col] = h1;
            } else {
                float* Y = (float*)Yall + (size_t)b * M * N;
                *(float2*)&Y[(size_t)row0 * N + col] = v0;
                *(float2*)&Y[(size_t)(row0 + 8) * N + col] = v1;
            }
        }
    }
}

// ---------------------------------------------------------------------------
// Launch
// ---------------------------------------------------------------------------
extern "C" void kernel_launch(void* const* d_in, const int* in_sizes, int n_in,
                              void* d_out, int out_size) {
    const float* x            = (const float*)d_in[0];
    const int*   view_ids     = (const int*)d_in[1];
    const int*   visit_ids    = (const int*)d_in[2];
    const float* router_view  = (const float*)d_in[3];
    const float* router_visit = (const float*)d_in[4];
    const float* W1           = (const float*)d_in[5];
    const float* b1           = (const float*)d_in[6];
    const float* W2           = (const float*)d_in[7];
    const float* b2           = (const float*)d_in[8];
    float* out = (float*)d_out;

    const size_t out_elems = (size_t)B_ * L_ * D_;
    float* loss_ptr = ((size_t)out_size > out_elems) ? (out + out_elems) : nullptr;

    __half *h_ptr, *xh_ptr, *w1t_ptr, *w2t_ptr;
    cudaGetSymbolAddress((void**)&h_ptr,   g_h);
    cudaGetSymbolAddress((void**)&xh_ptr,  g_xh);
    cudaGetSymbolAddress((void**)&w1t_ptr, g_w1t);
    cudaGetSymbolAddress((void**)&w2t_ptr, g_w2t);

    const int SMEM_BYTES = STAGES * STAGE_BYTES;   // 110592
    cudaFuncSetAttribute((const void*)gemm_f16_mma<true>,
                         cudaFuncAttributeMaxDynamicSharedMemorySize, SMEM_BYTES);
    cudaFuncSetAttribute((const void*)gemm_f16_mma<false>,
                         cudaFuncAttributeMaxDynamicSharedMemorySize, SMEM_BYTES);

    // Router + loss (fills g_top1)
    router_kernel<<<1, 1>>>(view_ids, visit_ids, router_view, router_visit, loss_ptr);

    // Prep: round x to fp16; transpose + round W1, W2 (to N x K, K-major, fp16)
    round_x_half<<<1024, 256>>>((const float4*)x, (uint2*)xh_ptr, (int)(out_elems / 4));
    transpose_half<<<dim3(DFF_ / 32, D_ / 32, E_), dim3(32, 8)>>>(W1, w1t_ptr, D_, DFF_);
    transpose_half<<<dim3(D_ / 32, DFF_ / 32, E_), dim3(32, 8)>>>(W2, w2t_ptr, DFF_, D_);

    // GEMM1: h = fp16(relu(x @ W1 + b1))   M=1024, N=2048, K=512
    gemm_f16_mma<true><<<dim3(DFF_ / 128, L_ / 128, B_), 256, SMEM_BYTES>>>(
        xh_ptr, w1t_ptr, b1, h_ptr, L_, DFF_, D_);

    // GEMM2: out = h @ W2 + b2             M=1024, N=512, K=2048
    gemm_f16_mma<false><<<dim3(D_ / 128, L_ / 128, B_), 256, SMEM_BYTES>>>(
        h_ptr, w2t_ptr, b2, out, L_, D_, DFF_);
}

// round 5
// speedup vs baseline: 5.9225x; 1.2033x over previous
#include <cuda_runtime.h>
#include <cuda_fp16.h>
#include <math.h>
#include <stdint.h>

#define B_   16
#define L_   1024
#define D_   512
#define E_   8
#define DFF_ 2048

// ---------------------------------------------------------------------------
// Scratch (static __device__ — no allocations allowed)
// ---------------------------------------------------------------------------
__device__ int    g_top1[B_];
__device__ __half g_h  [(size_t)B_ * L_ * DFF_];   // relu(x@W1+b1), fp16
__device__ __half g_xh [(size_t)B_ * L_ * D_];     // x rounded to fp16
__device__ __half g_w1t[(size_t)E_ * DFF_ * D_];   // W1^T per expert (N x K), fp16
__device__ __half g_w2t[(size_t)E_ * D_ * DFF_];   // W2^T per expert (N x K), fp16

__device__ __forceinline__ uint32_t smem_to_u32(const void* p) {
    uint32_t a;
    asm("{ .reg .u64 t; cvta.to.shared.u64 t, %1; cvt.u32.u64 %0, t; }" : "=r"(a) : "l"(p));
    return a;
}
__device__ __forceinline__ void cp_async16(uint32_t dst, const void* src) {
    asm volatile("cp.async.cg.shared.global [%0], [%1], 16;" :: "r"(dst), "l"(src) : "memory");
}
__device__ __forceinline__ void ldmatrix_x4(uint32_t& r0, uint32_t& r1, uint32_t& r2,
                                            uint32_t& r3, uint32_t addr) {
    asm volatile("ldmatrix.sync.aligned.m8n8.x4.shared.b16 {%0,%1,%2,%3}, [%4];"
                 : "=r"(r0), "=r"(r1), "=r"(r2), "=r"(r3) : "r"(addr));
}
__device__ __forceinline__ void mma_f16(float& c0, float& c1, float& c2, float& c3,
                                        uint32_t a0, uint32_t a1, uint32_t a2, uint32_t a3,
                                        uint32_t b0, uint32_t b1) {
    asm volatile("mma.sync.aligned.m16n8k16.row.col.f32.f16.f16.f32 "
                 "{%0,%1,%2,%3}, {%4,%5,%6,%7}, {%8,%9}, {%0,%1,%2,%3};"
                 : "+f"(c0), "+f"(c1), "+f"(c2), "+f"(c3)
                 : "r"(a0), "r"(a1), "r"(a2), "r"(a3), "r"(b0), "r"(b1));
}

// ---------------------------------------------------------------------------
// Fused prep: router + x->fp16 round + W1/W2 transpose->fp16, one kernel.
// Grid layout (1D, 256 threads each):
//   [0, 8192)       : W1 transpose tiles  (8 experts x 64 x 16 32x32-tiles)
//   [8192, 16384)   : W2 transpose tiles  (8 experts x 16 x 64 tiles)
//   [16384, 18432)  : x fp16 rounding (grid-stride over 2M float4)
//   [18432]         : router + balance loss (1 thread)
// ---------------------------------------------------------------------------
#define PREP_W1_BLKS 8192
#define PREP_W2_BLKS 8192
#define PREP_X_BLKS  2048
#define PREP_TOTAL   (PREP_W1_BLKS + PREP_W2_BLKS + PREP_X_BLKS + 1)

__global__ void __launch_bounds__(256)
prep_fused(const float* __restrict__ x,
           const float* __restrict__ W1, const float* __restrict__ W2,
           const int* __restrict__ view_ids, const int* __restrict__ visit_ids,
           const float* __restrict__ router_view, const float* __restrict__ router_visit,
           float* loss_out,
           __half* __restrict__ xh, __half* __restrict__ w1t, __half* __restrict__ w2t) {
    const int bid = blockIdx.x;
    const int tid = threadIdx.x;

    if (bid < PREP_W1_BLKS + PREP_W2_BLKS) {
        __shared__ float t[32][33];
        const float* in;
        __half* out;
        int R, C, r0, c0;
        if (bid < PREP_W1_BLKS) {
            const int e = bid >> 10, tt = bid & 1023;
            R = D_; C = DFF_;
            r0 = (tt >> 6) * 32; c0 = (tt & 63) * 32;
            in  = W1  + (size_t)e * R * C;
            out = w1t + (size_t)e * C * R;
        } else {
            const int bb = bid - PREP_W1_BLKS;
            const int e = bb >> 10, tt = bb & 1023;
            R = DFF_; C = D_;
            r0 = (tt >> 4) * 32; c0 = (tt & 15) * 32;
            in  = W2  + (size_t)e * R * C;
            out = w2t + (size_t)e * C * R;
        }
        const int tx = tid & 31, ty = tid >> 5;
#pragma unroll
        for (int i = ty; i < 32; i += 8)
            t[i][tx] = in[(size_t)(r0 + i) * C + c0 + tx];
        __syncthreads();
#pragma unroll
        for (int i = ty; i < 32; i += 8)
            out[(size_t)(c0 + i) * R + r0 + tx] = __float2half_rn(t[tx][i]);
        return;
    }

    if (bid < PREP_W1_BLKS + PREP_W2_BLKS + PREP_X_BLKS) {
        const int xb = bid - (PREP_W1_BLKS + PREP_W2_BLKS);
        const int n4 = (B_ * L_ * D_) / 4;       // 2,097,152 float4
        const float4* in = (const float4*)x;
        uint2* out = (uint2*)xh;
        for (int i = xb * 256 + tid; i < n4; i += PREP_X_BLKS * 256) {
            const float4 v = in[i];
            const __half2 h01 = __floats2half2_rn(v.x, v.y);
            const __half2 h23 = __floats2half2_rn(v.z, v.w);
            uint2 o;
            o.x = *(const uint32_t*)&h01;
            o.y = *(const uint32_t*)&h23;
            out[i] = o;
        }
        return;
    }

    // Router + balance loss (1 thread)
    if (tid == 0) {
        float load[E_];
#pragma unroll
        for (int e = 0; e < E_; e++) load[e] = 0.0f;
        for (int b = 0; b < B_; b++) {
            const int vi = view_ids[b];
            const int vs = visit_ids[b];
            float lg[E_];
            float m = -1e30f; int am = 0;
#pragma unroll
            for (int e = 0; e < E_; e++) {
                lg[e] = router_view[vi * E_ + e] + router_visit[vs * E_ + e];
                if (lg[e] > m) { m = lg[e]; am = e; }
            }
            g_top1[b] = am;
            float s = 0.0f;
#pragma unroll
            for (int e = 0; e < E_; e++) { lg[e] = expf(lg[e] - m); s += lg[e]; }
            const float inv = 1.0f / s;
#pragma unroll
            for (int e = 0; e < E_; e++) load[e] += lg[e] * inv;
        }
        float loss = 0.0f;
#pragma unroll
        for (int e = 0; e < E_; e++) {
            const float ld = load[e] * (1.0f / (float)B_);
            loss -= ld * logf(ld);
        }
        if (loss_out) *loss_out = loss;
    }
}

// ---------------------------------------------------------------------------
// FP16 tensor-core GEMM via mma.sync m16n8k16 (fp32 accumulate):
//   Y[b] = act( A[b] (MxK row-major fp16) @ B[e_b]^T (NxK K-major fp16) + bias )
// CTA tile 128x256x64, 8 warps in 2x4, warp tile 64x64. 3-stage cp.async.
// Smem rows padded to 144B -> conflict-free ldmatrix & async stores.
// ---------------------------------------------------------------------------
#define STAGES 3
#define A_TILE_BYTES 18432               // 128 rows * 144B
#define B_TILE_BYTES 36864               // 256 rows * 144B
#define STAGE_BYTES  55296               // A + B

template <bool OUT_HALF>
__global__ void __launch_bounds__(256, 1)
gemm_f16_mma(const __half* __restrict__ Aall, const __half* __restrict__ Ball,
             const float* __restrict__ biasAll, void* __restrict__ Yall,
             int M, int N, int K) {
    extern __shared__ __align__(128) char smem[];
    const uint32_t smem_base = smem_to_u32(smem);

    const int tid  = threadIdx.x;
    const int wid  = tid >> 5;
    const int lane = tid & 31;
    const int mbase = (wid & 1) * 64;    // 2 warp rows
    const int nbase = (wid >> 1) * 64;   // 4 warp cols

    const int b = blockIdx.z;
    const int e = g_top1[b];
    const int block_row = blockIdx.y * 128;
    const int block_col = blockIdx.x * 256;

    const __half* Aptr = Aall + (size_t)b * M * K + (size_t)block_row * K;
    const __half* Bptr = Ball + (size_t)e * N * K + (size_t)block_col * K;
    const float* bias = biasAll + (size_t)e * N + block_col;

    const int T = K >> 6;                // BK = 64

    // -------- cp.async loader: A 128x64h + B 256x64h, 3072 16B chunks -------
    auto load_tile = [&](int t, int stage) {
        const __half* Ag = Aptr + t * 64;
        const __half* Bg = Bptr + t * 64;
        const uint32_t sa = smem_base + stage * STAGE_BYTES;
        const uint32_t sb = sa + A_TILE_BYTES;
#pragma unroll
        for (int i = 0; i < 4; i++) {    // A: idx 0..1023
            const int idx = tid + i * 256;
            const int r = idx >> 3, q = idx & 7;
            cp_async16(sa + r * 144 + q * 16, Ag + (size_t)r * K + q * 8);
        }
#pragma unroll
        for (int i = 0; i < 8; i++) {    // B: idx 0..2047
            const int idx = tid + i * 256;
            const int r = idx >> 3, q = idx & 7;
            cp_async16(sb + r * 144 + q * 16, Bg + (size_t)r * K + q * 8);
        }
        asm volatile("cp.async.commit_group;" ::: "memory");
    };

    float acc[4][8][4];
#pragma unroll
    for (int i = 0; i < 4; i++)
#pragma unroll
        for (int j = 0; j < 8; j++)
#pragma unroll
            for (int r = 0; r < 4; r++) acc[i][j][r] = 0.0f;

#pragma unroll
    for (int s = 0; s < STAGES - 1; s++)
        if (s < T) load_tile(s, s);

    // ldmatrix lane addressing (byte offsets; k+8 halves = +16B)
    const int a_row = mbase + (lane & 15);
    const int a_coff = ((lane >> 4) & 1) * 16;
    const int b_row_off = (lane & 7) + ((lane >> 4) & 1) * 8;
    const int b_coff = ((lane >> 3) & 1) * 16;

    for (int t = 0; t < T; t++) {
        if (t + STAGES - 1 < T) load_tile(t + STAGES - 1, (t + STAGES - 1) % STAGES);

        const int remaining = T - 1 - t;
        if (remaining >= 2)      asm volatile("cp.async.wait_group 2;" ::: "memory");
        else if (remaining == 1) asm volatile("cp.async.wait_group 1;" ::: "memory");
        else                     asm volatile("cp.async.wait_group 0;" ::: "memory");
        __syncthreads();

        const uint32_t sa = smem_base + (t % STAGES) * STAGE_BYTES;
        const uint32_t sb = sa + A_TILE_BYTES;

#pragma unroll
        for (int ks = 0; ks < 4; ks++) {
            const int kc = ks * 32;                      // 16 halves per kstep
            uint32_t af[4][4];
#pragma unroll
            for (int mt = 0; mt < 4; mt++) {
                const uint32_t addr = sa + (a_row + mt * 16) * 144 + kc + a_coff;
                ldmatrix_x4(af[mt][0], af[mt][1], af[mt][2], af[mt][3], addr);
            }
            uint32_t bf[8][2];
#pragma unroll
            for (int p = 0; p < 4; p++) {
                const uint32_t addr = sb + (nbase + p * 16 + b_row_off) * 144 + kc + b_coff;
                ldmatrix_x4(bf[2 * p][0], bf[2 * p][1], bf[2 * p + 1][0], bf[2 * p + 1][1], addr);
            }
#pragma unroll
            for (int mt = 0; mt < 4; mt++)
#pragma unroll
                for (int nt = 0; nt < 8; nt++)
                    mma_f16(acc[mt][nt][0], acc[mt][nt][1], acc[mt][nt][2], acc[mt][nt][3],
                            af[mt][0], af[mt][1], af[mt][2], af[mt][3],
                            bf[nt][0], bf[nt][1]);
        }
        __syncthreads();
    }

    // -------- Epilogue --------
    const int gid = lane >> 2;          // 0..7
    const int tig = lane & 3;           // 0..3
#pragma unroll
    for (int nt = 0; nt < 8; nt++) {
        const int coll = nbase + nt * 8 + 2 * tig;
        const float2 bv = *(const float2*)&bias[coll];
        const int col = block_col + coll;
#pragma unroll
        for (int mt = 0; mt < 4; mt++) {
            const int row0 = block_row + mbase + mt * 16 + gid;
            float2 v0, v1;
            v0.x = acc[mt][nt][0] + bv.x;
            v0.y = acc[mt][nt][1] + bv.y;
            v1.x = acc[mt][nt][2] + bv.x;
            v1.y = acc[mt][nt][3] + bv.y;
            if (OUT_HALF) {
                __half* Y = (__half*)Yall + (size_t)b * M * N;
                const __half2 h0 = __floats2half2_rn(fmaxf(v0.x, 0.0f), fmaxf(v0.y, 0.0f));
                const __half2 h1 = __floats2half2_rn(fmaxf(v1.x, 0.0f), fmaxf(v1.y, 0.0f));
                *(__half2*)&Y[(size_t)row0 * N + col] = h0;
                *(__half2*)&Y[(size_t)(row0 + 8) * N + col] = h1;
            } else {
                float* Y = (float*)Yall + (size_t)b * M * N;
                *(float2*)&Y[(size_t)row0 * N + col] = v0;
                *(float2*)&Y[(size_t)(row0 + 8) * N + col] = v1;
            }
        }
    }
}

// ---------------------------------------------------------------------------
// Launch
// ---------------------------------------------------------------------------
extern "C" void kernel_launch(void* const* d_in, const int* in_sizes, int n_in,
                              void* d_out, int out_size) {
    const float* x            = (const float*)d_in[0];
    const int*   view_ids     = (const int*)d_in[1];
    const int*   visit_ids    = (const int*)d_in[2];
    const float* router_view  = (const float*)d_in[3];
    const float* router_visit = (const float*)d_in[4];
    const float* W1           = (const float*)d_in[5];
    const float* b1           = (const float*)d_in[6];
    const float* W2           = (const float*)d_in[7];
    const float* b2           = (const float*)d_in[8];
    float* out = (float*)d_out;

    const size_t out_elems = (size_t)B_ * L_ * D_;
    float* loss_ptr = ((size_t)out_size > out_elems) ? (out + out_elems) : nullptr;

    __half *h_ptr, *xh_ptr, *w1t_ptr, *w2t_ptr;
    cudaGetSymbolAddress((void**)&h_ptr,   g_h);
    cudaGetSymbolAddress((void**)&xh_ptr,  g_xh);
    cudaGetSymbolAddress((void**)&w1t_ptr, g_w1t);
    cudaGetSymbolAddress((void**)&w2t_ptr, g_w2t);

    const int SMEM_BYTES = STAGES * STAGE_BYTES;   // 165888
    cudaFuncSetAttribute((const void*)gemm_f16_mma<true>,
                         cudaFuncAttributeMaxDynamicSharedMemorySize, SMEM_BYTES);
    cudaFuncSetAttribute((const void*)gemm_f16_mma<false>,
                         cudaFuncAttributeMaxDynamicSharedMemorySize, SMEM_BYTES);

    // Fused prep: router + x fp16 round + W1/W2 transpose (all parallel)
    prep_fused<<<PREP_TOTAL, 256>>>(x, W1, W2, view_ids, visit_ids,
                                    router_view, router_visit, loss_ptr,
                                    xh_ptr, w1t_ptr, w2t_ptr);

    // GEMM1: h = fp16(relu(x @ W1 + b1))   M=1024, N=2048, K=512
    gemm_f16_mma<true><<<dim3(DFF_ / 256, L_ / 128, B_), 256, SMEM_BYTES>>>(
        xh_ptr, w1t_ptr, b1, h_ptr, L_, DFF_, D_);

    // GEMM2: out = h @ W2 + b2             M=1024, N=512, K=2048
    gemm_f16_mma<false><<<dim3(D_ / 256, L_ / 128, B_), 256, SMEM_BYTES>>>(
        h_ptr, w2t_ptr, b2, out, L_, D_, DFF_);
}

// round 6
// speedup vs baseline: 6.3418x; 1.0708x over previous
#include <cuda_runtime.h>
#include <cuda_fp16.h>
#include <math.h>
#include <stdint.h>

#define B_   16
#define L_   1024
#define D_   512
#define E_   8
#define DFF_ 2048

// ---------------------------------------------------------------------------
// Scratch (static __device__ — no allocations allowed)
// ---------------------------------------------------------------------------
__device__ int    g_top1[B_];
__device__ __half g_h  [(size_t)B_ * L_ * DFF_];   // relu(x@W1+b1), fp16
__device__ __half g_xh [(size_t)B_ * L_ * D_];     // x rounded to fp16
__device__ __half g_w1t[(size_t)E_ * DFF_ * D_];   // W1^T per expert (N x K), fp16
__device__ __half g_w2t[(size_t)E_ * D_ * DFF_];   // W2^T per expert (N x K), fp16

__device__ __forceinline__ uint32_t smem_to_u32(const void* p) {
    uint32_t a;
    asm("{ .reg .u64 t; cvta.to.shared.u64 t, %1; cvt.u32.u64 %0, t; }" : "=r"(a) : "l"(p));
    return a;
}
__device__ __forceinline__ void cp_async16(uint32_t dst, const void* src) {
    asm volatile("cp.async.cg.shared.global [%0], [%1], 16;" :: "r"(dst), "l"(src) : "memory");
}
__device__ __forceinline__ void ldmatrix_x4(uint32_t& r0, uint32_t& r1, uint32_t& r2,
                                            uint32_t& r3, uint32_t addr) {
    asm volatile("ldmatrix.sync.aligned.m8n8.x4.shared.b16 {%0,%1,%2,%3}, [%4];"
                 : "=r"(r0), "=r"(r1), "=r"(r2), "=r"(r3) : "r"(addr));
}
__device__ __forceinline__ void mma_f16(float& c0, float& c1, float& c2, float& c3,
                                        uint32_t a0, uint32_t a1, uint32_t a2, uint32_t a3,
                                        uint32_t b0, uint32_t b1) {
    asm volatile("mma.sync.aligned.m16n8k16.row.col.f32.f16.f16.f32 "
                 "{%0,%1,%2,%3}, {%4,%5,%6,%7}, {%8,%9}, {%0,%1,%2,%3};"
                 : "+f"(c0), "+f"(c1), "+f"(c2), "+f"(c3)
                 : "r"(a0), "r"(a1), "r"(a2), "r"(a3), "r"(b0), "r"(b1));
}

// ---------------------------------------------------------------------------
// Fused prep: router + x->fp16 round + W1/W2 transpose->fp16, one kernel.
// ---------------------------------------------------------------------------
#define PREP_W1_BLKS 8192
#define PREP_W2_BLKS 8192
#define PREP_X_BLKS  2048
#define PREP_TOTAL   (PREP_W1_BLKS + PREP_W2_BLKS + PREP_X_BLKS + 1)

__global__ void __launch_bounds__(256)
prep_fused(const float* __restrict__ x,
           const float* __restrict__ W1, const float* __restrict__ W2,
           const int* __restrict__ view_ids, const int* __restrict__ visit_ids,
           const float* __restrict__ router_view, const float* __restrict__ router_visit,
           float* loss_out,
           __half* __restrict__ xh, __half* __restrict__ w1t, __half* __restrict__ w2t) {
    const int bid = blockIdx.x;
    const int tid = threadIdx.x;

    if (bid < PREP_W1_BLKS + PREP_W2_BLKS) {
        __shared__ float t[32][33];
        const float* in;
        __half* out;
        int R, C, r0, c0;
        if (bid < PREP_W1_BLKS) {
            const int e = bid >> 10, tt = bid & 1023;
            R = D_; C = DFF_;
            r0 = (tt >> 6) * 32; c0 = (tt & 63) * 32;
            in  = W1  + (size_t)e * R * C;
            out = w1t + (size_t)e * C * R;
        } else {
            const int bb = bid - PREP_W1_BLKS;
            const int e = bb >> 10, tt = bb & 1023;
            R = DFF_; C = D_;
            r0 = (tt >> 4) * 32; c0 = (tt & 15) * 32;
            in  = W2  + (size_t)e * R * C;
            out = w2t + (size_t)e * C * R;
        }
        const int tx = tid & 31, ty = tid >> 5;
#pragma unroll
        for (int i = ty; i < 32; i += 8)
            t[i][tx] = in[(size_t)(r0 + i) * C + c0 + tx];
        __syncthreads();
#pragma unroll
        for (int i = ty; i < 32; i += 8)
            out[(size_t)(c0 + i) * R + r0 + tx] = __float2half_rn(t[tx][i]);
        return;
    }

    if (bid < PREP_W1_BLKS + PREP_W2_BLKS + PREP_X_BLKS) {
        const int xb = bid - (PREP_W1_BLKS + PREP_W2_BLKS);
        const int n4 = (B_ * L_ * D_) / 4;       // 2,097,152 float4
        const float4* in = (const float4*)x;
        uint2* out = (uint2*)xh;
        for (int i = xb * 256 + tid; i < n4; i += PREP_X_BLKS * 256) {
            const float4 v = in[i];
            const __half2 h01 = __floats2half2_rn(v.x, v.y);
            const __half2 h23 = __floats2half2_rn(v.z, v.w);
            uint2 o;
            o.x = *(const uint32_t*)&h01;
            o.y = *(const uint32_t*)&h23;
            out[i] = o;
        }
        return;
    }

    // Router + balance loss (1 thread)
    if (tid == 0) {
        float load[E_];
#pragma unroll
        for (int e = 0; e < E_; e++) load[e] = 0.0f;
        for (int b = 0; b < B_; b++) {
            const int vi = view_ids[b];
            const int vs = visit_ids[b];
            float lg[E_];
            float m = -1e30f; int am = 0;
#pragma unroll
            for (int e = 0; e < E_; e++) {
                lg[e] = router_view[vi * E_ + e] + router_visit[vs * E_ + e];
                if (lg[e] > m) { m = lg[e]; am = e; }
            }
            g_top1[b] = am;
            float s = 0.0f;
#pragma unroll
            for (int e = 0; e < E_; e++) { lg[e] = expf(lg[e] - m); s += lg[e]; }
            const float inv = 1.0f / s;
#pragma unroll
            for (int e = 0; e < E_; e++) load[e] += lg[e] * inv;
        }
        float loss = 0.0f;
#pragma unroll
        for (int e = 0; e < E_; e++) {
            const float ld = load[e] * (1.0f / (float)B_);
            loss -= ld * logf(ld);
        }
        if (loss_out) *loss_out = loss;
    }
}

// ---------------------------------------------------------------------------
// FP16 tensor-core GEMM via mma.sync m16n8k16 (fp32 accumulate):
//   Y[b] = act( A[b] (MxK row-major fp16) @ B[e_b]^T (NxK K-major fp16) + bias )
// CTA tile 128x128x64, 8 warps in 2x4, warp tile 64x32. 3-stage cp.async,
// 2 CTAs/SM (110.6KB smem each), ONE __syncthreads per ktile.
// ---------------------------------------------------------------------------
#define STAGES 3
#define A_TILE_BYTES 18432               // 128 rows * 144B
#define STAGE_BYTES  36864               // A + B (128 rows each)

template <bool OUT_HALF>
__global__ void __launch_bounds__(256, 2)
gemm_f16_mma(const __half* __restrict__ Aall, const __half* __restrict__ Ball,
             const float* __restrict__ biasAll, void* __restrict__ Yall,
             int M, int N, int K) {
    extern __shared__ __align__(128) char smem[];
    const uint32_t smem_base = smem_to_u32(smem);

    const int tid  = threadIdx.x;
    const int wid  = tid >> 5;
    const int lane = tid & 31;
    const int mbase = (wid & 1) * 64;    // 2 warp rows
    const int nbase = (wid >> 1) * 32;   // 4 warp cols

    const int b = blockIdx.z;
    const int e = g_top1[b];
    const int block_row = blockIdx.y * 128;
    const int block_col = blockIdx.x * 128;

    const __half* Aptr = Aall + (size_t)b * M * K + (size_t)block_row * K;
    const __half* Bptr = Ball + (size_t)e * N * K + (size_t)block_col * K;
    const float* bias = biasAll + (size_t)e * N + block_col;

    const int T = K >> 6;                // BK = 64

    // -------- cp.async loader: A 128x64h + B 128x64h, 2048 16B chunks -------
    auto load_tile = [&](int t, int stage) {
        const __half* Ag = Aptr + t * 64;
        const __half* Bg = Bptr + t * 64;
        const uint32_t sa = smem_base + stage * STAGE_BYTES;
        const uint32_t sb = sa + A_TILE_BYTES;
#pragma unroll
        for (int i = 0; i < 4; i++) {
            const int idx = tid + i * 256;
            const int r = idx >> 3, q = idx & 7;
            cp_async16(sa + r * 144 + q * 16, Ag + (size_t)r * K + q * 8);
            cp_async16(sb + r * 144 + q * 16, Bg + (size_t)r * K + q * 8);
        }
        asm volatile("cp.async.commit_group;" ::: "memory");
    };

    float acc[4][4][4];
#pragma unroll
    for (int i = 0; i < 4; i++)
#pragma unroll
        for (int j = 0; j < 4; j++)
#pragma unroll
            for (int r = 0; r < 4; r++) acc[i][j][r] = 0.0f;

#pragma unroll
    for (int s = 0; s < STAGES - 1; s++)
        if (s < T) load_tile(s, s);

    // ldmatrix lane addressing (byte offsets; k+8 halves = +16B)
    const int a_row = mbase + (lane & 15);
    const int a_coff = ((lane >> 4) & 1) * 16;
    const int b_row_off = (lane & 7) + ((lane >> 4) & 1) * 8;
    const int b_coff = ((lane >> 3) & 1) * 16;

    for (int t = 0; t < T; t++) {
        // Stage t must be resident: allow 1 pending group unless this is the last.
        if (t < T - 1) asm volatile("cp.async.wait_group 1;" ::: "memory");
        else           asm volatile("cp.async.wait_group 0;" ::: "memory");
        __syncthreads();   // single barrier per ktile

        // Issue next load (overwrites stage consumed in iter t-1; all reads of
        // it completed before the barrier above — ldmatrix results land in
        // registers before the issuing warp reaches the barrier).
        if (t + STAGES - 1 < T) load_tile(t + STAGES - 1, (t + STAGES - 1) % STAGES);

        const uint32_t sa = smem_base + (t % STAGES) * STAGE_BYTES;
        const uint32_t sb = sa + A_TILE_BYTES;

#pragma unroll
        for (int ks = 0; ks < 4; ks++) {
            const int kc = ks * 32;                      // 16 halves per kstep
            uint32_t af[4][4];
#pragma unroll
            for (int mt = 0; mt < 4; mt++) {
                const uint32_t addr = sa + (a_row + mt * 16) * 144 + kc + a_coff;
                ldmatrix_x4(af[mt][0], af[mt][1], af[mt][2], af[mt][3], addr);
            }
            uint32_t bf[4][2];
#pragma unroll
            for (int p = 0; p < 2; p++) {
                const uint32_t addr = sb + (nbase + p * 16 + b_row_off) * 144 + kc + b_coff;
                ldmatrix_x4(bf[2 * p][0], bf[2 * p][1], bf[2 * p + 1][0], bf[2 * p + 1][1], addr);
            }
#pragma unroll
            for (int mt = 0; mt < 4; mt++)
#pragma unroll
                for (int nt = 0; nt < 4; nt++)
                    mma_f16(acc[mt][nt][0], acc[mt][nt][1], acc[mt][nt][2], acc[mt][nt][3],
                            af[mt][0], af[mt][1], af[mt][2], af[mt][3],
                            bf[nt][0], bf[nt][1]);
        }
    }

    // -------- Epilogue --------
    const int gid = lane >> 2;          // 0..7
    const int tig = lane & 3;           // 0..3
#pragma unroll
    for (int nt = 0; nt < 4; nt++) {
        const int coll = nbase + nt * 8 + 2 * tig;
        const float2 bv = *(const float2*)&bias[coll];
        const int col = block_col + coll;
#pragma unroll
        for (int mt = 0; mt < 4; mt++) {
            const int row0 = block_row + mbase + mt * 16 + gid;
            float2 v0, v1;
            v0.x = acc[mt][nt][0] + bv.x;
            v0.y = acc[mt][nt][1] + bv.y;
            v1.x = acc[mt][nt][2] + bv.x;
            v1.y = acc[mt][nt][3] + bv.y;
            if (OUT_HALF) {
                __half* Y = (__half*)Yall + (size_t)b * M * N;
                const __half2 h0 = __floats2half2_rn(fmaxf(v0.x, 0.0f), fmaxf(v0.y, 0.0f));
                const __half2 h1 = __floats2half2_rn(fmaxf(v1.x, 0.0f), fmaxf(v1.y, 0.0f));
                *(__half2*)&Y[(size_t)row0 * N + col] = h0;
                *(__half2*)&Y[(size_t)(row0 + 8) * N + col] = h1;
            } else {
                float* Y = (float*)Yall + (size_t)b * M * N;
                *(float2*)&Y[(size_t)row0 * N + col] = v0;
                *(float2*)&Y[(size_t)(row0 + 8) * N + col] = v1;
            }
        }
    }
}

// ---------------------------------------------------------------------------
// Launch
// ---------------------------------------------------------------------------
extern "C" void kernel_launch(void* const* d_in, const int* in_sizes, int n_in,
                              void* d_out, int out_size) {
    const float* x            = (const float*)d_in[0];
    const int*   view_ids     = (const int*)d_in[1];
    const int*   visit_ids    = (const int*)d_in[2];
    const float* router_view  = (const float*)d_in[3];
    const float* router_visit = (const float*)d_in[4];
    const float* W1           = (const float*)d_in[5];
    const float* b1           = (const float*)d_in[6];
    const float* W2           = (const float*)d_in[7];
    const float* b2           = (const float*)d_in[8];
    float* out = (float*)d_out;

    const size_t out_elems = (size_t)B_ * L_ * D_;
    float* loss_ptr = ((size_t)out_size > out_elems) ? (out + out_elems) : nullptr;

    __half *h_ptr, *xh_ptr, *w1t_ptr, *w2t_ptr;
    cudaGetSymbolAddress((void**)&h_ptr,   g_h);
    cudaGetSymbolAddress((void**)&xh_ptr,  g_xh);
    cudaGetSymbolAddress((void**)&w1t_ptr, g_w1t);
    cudaGetSymbolAddress((void**)&w2t_ptr, g_w2t);

    const int SMEM_BYTES = STAGES * STAGE_BYTES;   // 110592 -> 2 CTAs/SM
    cudaFuncSetAttribute((const void*)gemm_f16_mma<true>,
                         cudaFuncAttributeMaxDynamicSharedMemorySize, SMEM_BYTES);
    cudaFuncSetAttribute((const void*)gemm_f16_mma<false>,
                         cudaFuncAttributeMaxDynamicSharedMemorySize, SMEM_BYTES);

    // Fused prep: router + x fp16 round + W1/W2 transpose (all parallel)
    prep_fused<<<PREP_TOTAL, 256>>>(x, W1, W2, view_ids, visit_ids,
                                    router_view, router_visit, loss_ptr,
                                    xh_ptr, w1t_ptr, w2t_ptr);

    // GEMM1: h = fp16(relu(x @ W1 + b1))   M=1024, N=2048, K=512
    gemm_f16_mma<true><<<dim3(DFF_ / 128, L_ / 128, B_), 256, SMEM_BYTES>>>(
        xh_ptr, w1t_ptr, b1, h_ptr, L_, DFF_, D_);

    // GEMM2: out = h @ W2 + b2             M=1024, N=512, K=2048
    gemm_f16_mma<false><<<dim3(D_ / 128, L_ / 128, B_), 256, SMEM_BYTES>>>(
        h_ptr, w2t_ptr, b2, out, L_, D_, DFF_);
}